// round 14
// baseline (speedup 1.0000x reference)
#include <cuda_runtime.h>
#include <cuda_fp16.h>
#include <math.h>
#include <stdint.h>

#define NN_ 4096
#define EE_ 262144
#define HID_ 256
#define DOUT_ 128
#define HEADS_ 4
#define DH_ 64
#define L_ 4096
#define FBM_ 64
#define FBN_ 128
#define NT_ (L_ / FBN_)
#define KST_ 36
#define TILEB_ (128 * KST_ * 4)
#define STAGEB_ (2 * TILEB_)
#define LOG2E_ 1.4426950408889634f

// ---------------- scratch (all static __device__, no allocations) ----------------
__device__ float g_deg[NN_];
__device__ float g_dinv[NN_];
__device__ int   g_cnt[NN_];
__device__ int   g_rowptr[NN_ + 1];
__device__ int   g_fill[NN_];
__device__ int   g_src[EE_];
__device__ float g_w[EE_];

__device__ float g_h[NN_ * HID_];
__device__ float g_a[NN_ * HID_];
__device__ float g_b[NN_ * HID_];
__device__ __half g_attnh[NN_ * HID_];
__device__ __half g_qkvh[NN_ * 3 * HID_];
__device__ float g_w1t[HID_ * 256];
__device__ float g_w2t[HID_ * HID_];
__device__ float g_w3t[DOUT_ * HID_];

// ---------------- preprocessing ----------------
__global__ void k_init() {
    int i = blockIdx.x * blockDim.x + threadIdx.x;
    if (i < NN_) { g_deg[i] = 1.0f; g_cnt[i] = 0; }
}

__global__ void k_deg(const int* __restrict__ ei, const float* __restrict__ ew) {
    int e = blockIdx.x * blockDim.x + threadIdx.x;
    if (e < EE_) {
        int c = ei[EE_ + e];
        atomicAdd(&g_deg[c], ew[e]);
        atomicAdd(&g_cnt[c], 1);
    }
}

__global__ void k_dinv() {
    int i = blockIdx.x * blockDim.x + threadIdx.x;
    if (i < NN_) {
        float d = g_deg[i];
        g_dinv[i] = (d > 0.f) ? rsqrtf(d) : 0.f;
    }
}

// warp-shuffle exclusive scan of g_cnt (4096) -> g_rowptr / g_fill. 256 threads.
__global__ void k_scan() {
    __shared__ int wsum[8];
    int t = threadIdx.x;
    int lane = t & 31, w = t >> 5;
    int base = t * 16;
    int v[16], s = 0;
#pragma unroll
    for (int i = 0; i < 16; i++) { v[i] = g_cnt[base + i]; s += v[i]; }
    int run = s;
#pragma unroll
    for (int off = 1; off < 32; off <<= 1) {
        int x = __shfl_up_sync(0xffffffffu, run, off);
        if (lane >= off) run += x;
    }
    if (lane == 31) wsum[w] = run;
    __syncthreads();
    if (w == 0) {
        int x = (lane < 8) ? wsum[lane] : 0;
#pragma unroll
        for (int off = 1; off < 8; off <<= 1) {
            int y = __shfl_up_sync(0xffffffffu, x, off);
            if (lane >= off) x += y;
        }
        if (lane < 8) wsum[lane] = x;
    }
    __syncthreads();
    int excl = run - s + (w ? wsum[w - 1] : 0);
#pragma unroll
    for (int i = 0; i < 16; i++) {
        g_rowptr[base + i] = excl;
        g_fill[base + i] = excl;
        excl += v[i];
    }
    if (t == 255) g_rowptr[NN_] = excl;
}

__global__ void k_fill(const int* __restrict__ ei, const float* __restrict__ ew) {
    int e = blockIdx.x * blockDim.x + threadIdx.x;
    if (e < EE_) {
        int r = ei[e];
        int c = ei[EE_ + e];
        int pos = atomicAdd(&g_fill[c], 1);
        g_src[pos] = r;
        g_w[pos] = g_dinv[r] * ew[e] * g_dinv[c];
    }
}

// Three transposes in one launch: z=0 W1[256,256], z=1 W2[256,256], z=2 W3[256,128]
__global__ void k_transpose3(const float* __restrict__ W1, float* __restrict__ W1T,
                             const float* __restrict__ W2, float* __restrict__ W2T,
                             const float* __restrict__ W3, float* __restrict__ W3T) {
    __shared__ float tile[32][33];
    const float* W;
    float* WT;
    int R, C;
    if (blockIdx.z == 0)      { W = W1; WT = W1T; R = 256; C = HID_; }
    else if (blockIdx.z == 1) { W = W2; WT = W2T; R = HID_; C = HID_; }
    else                      { W = W3; WT = W3T; R = HID_; C = DOUT_; }
    int c0 = blockIdx.x * 32, r0 = blockIdx.y * 32;
    if (c0 >= C || r0 >= R) return;
    for (int i = threadIdx.y; i < 32; i += 8)
        tile[i][threadIdx.x] = W[(size_t)(r0 + i) * C + c0 + threadIdx.x];
    __syncthreads();
    for (int i = threadIdx.y; i < 32; i += 8)
        WT[(size_t)(c0 + i) * R + r0 + threadIdx.x] = tile[threadIdx.x][i];
}

// ---------------- fp16 / mma helpers ----------------
__device__ __forceinline__ uint32_t packhf(float lo, float hi) {
    uint32_t u;
    asm("cvt.rn.f16x2.f32 %0, %1, %2;" : "=r"(u) : "f"(hi), "f"(lo));
    return u;
}

__device__ __forceinline__ uint32_t ex2h2(uint32_t x) {
    uint32_t y;
    asm("ex2.approx.f16x2 %0, %1;" : "=r"(y) : "r"(x));
    return y;
}

__device__ __forceinline__ uint32_t hmul2u(uint32_t a, uint32_t b) {
    uint32_t y;
    asm("mul.f16x2 %0, %1, %2;" : "=r"(y) : "r"(a), "r"(b));
    return y;
}

__device__ __forceinline__ void mma_f16(float c[4], const uint32_t a[4], uint32_t b0, uint32_t b1) {
    asm volatile(
        "mma.sync.aligned.m16n8k16.row.col.f32.f16.f16.f32 "
        "{%0,%1,%2,%3}, {%4,%5,%6,%7}, {%8,%9}, {%0,%1,%2,%3};"
        : "+f"(c[0]), "+f"(c[1]), "+f"(c[2]), "+f"(c[3])
        : "r"(a[0]), "r"(a[1]), "r"(a[2]), "r"(a[3]), "r"(b0), "r"(b1));
}

// fp16 accumulator variant: D/C are 2 packed f16x2 regs
__device__ __forceinline__ void mma_h16(uint32_t c[2], const uint32_t a[4], uint32_t b0, uint32_t b1) {
    asm volatile(
        "mma.sync.aligned.m16n8k16.row.col.f16.f16.f16.f16 "
        "{%0,%1}, {%2,%3,%4,%5}, {%6,%7}, {%0,%1};"
        : "+r"(c[0]), "+r"(c[1])
        : "r"(a[0]), "r"(a[1]), "r"(a[2]), "r"(a[3]), "r"(b0), "r"(b1));
}

__device__ __forceinline__ void ldsm4(uint32_t& r0, uint32_t& r1, uint32_t& r2, uint32_t& r3,
                                      uint32_t addr) {
    asm volatile("ldmatrix.sync.aligned.m8n8.x4.shared.b16 {%0,%1,%2,%3}, [%4];"
                 : "=r"(r0), "=r"(r1), "=r"(r2), "=r"(r3) : "r"(addr));
}

__device__ __forceinline__ void ldsm4t(uint32_t& r0, uint32_t& r1, uint32_t& r2, uint32_t& r3,
                                       uint32_t addr) {
    asm volatile("ldmatrix.sync.aligned.m8n8.x4.trans.shared.b16 {%0,%1,%2,%3}, [%4];"
                 : "=r"(r0), "=r"(r1), "=r"(r2), "=r"(r3) : "r"(addr));
}

__device__ __forceinline__ void cp16(uint32_t dst, const void* src) {
    asm volatile("cp.async.ca.shared.global [%0], [%1], 16;" :: "r"(dst), "l"(src));
}

// ---------------- fp16 tensor-core GEMM:  C = A @ B^T (+bias)(+relu) ----------------
// AHF=1: A is fp16 [M,K] (raw copy staging). AHF=0: A fp32 (cvt on staging).
template <int EPI, int OUTHF, int AHF>
__global__ void __launch_bounds__(256) tc_gemm(
    const void* __restrict__ Av, int lda,
    const float* __restrict__ B, int ldb,
    const float* __restrict__ bias,
    void* __restrict__ Cv, int ldc, int K)
{
    constexpr int BM = 128, BN = 64, BK = 32, ST = 20;
    __shared__ uint32_t As[BM * ST];
    __shared__ uint32_t Bs[BN * ST];

    const int bm = blockIdx.y * BM;
    const int bn = blockIdx.x * BN;
    const int tid = threadIdx.x;
    const int lane = tid & 31;
    const int warp = tid >> 5;
    const int wm = (warp & 3) * 32;
    const int wn = (warp >> 2) * 32;
    const int gr = lane >> 2;
    const int gc = lane & 3;

    float acc[2][4][4];
#pragma unroll
    for (int mt = 0; mt < 2; mt++)
#pragma unroll
        for (int nt = 0; nt < 4; nt++)
#pragma unroll
            for (int q = 0; q < 4; q++) acc[mt][nt][q] = 0.f;

    for (int kt = 0; kt < K; kt += BK) {
        if (AHF) {
            const __half* A = (const __half*)Av;
            const int m = tid >> 1;
            const int kh = (tid & 1) * 16;
            const uint4 v = *reinterpret_cast<const uint4*>(
                A + (size_t)(bm + m) * lda + kt + kh);
            uint32_t* s = &As[m * ST + kh / 2];
            s[0] = v.x; s[1] = v.y; s[2] = v.z; s[3] = v.w;
        } else {
            const float* A = (const float*)Av;
            const int m = tid >> 1;
            const int kh = (tid & 1) * 16;
            const float* p = A + (size_t)(bm + m) * lda + kt + kh;
            uint32_t* s = &As[m * ST + kh / 2];
#pragma unroll
            for (int j = 0; j < 4; j++) {
                float4 v = *reinterpret_cast<const float4*>(p + j * 4);
                s[j * 2 + 0] = packhf(v.x, v.y);
                s[j * 2 + 1] = packhf(v.z, v.w);
            }
        }
        {
            const int n = tid >> 2;
            const int kh = (tid & 3) * 8;
            const float* p = B + (size_t)(bn + n) * ldb + kt + kh;
            uint32_t* s = &Bs[n * ST + kh / 2];
            float4 v0 = *reinterpret_cast<const float4*>(p);
            float4 v1 = *reinterpret_cast<const float4*>(p + 4);
            s[0] = packhf(v0.x, v0.y);
            s[1] = packhf(v0.z, v0.w);
            s[2] = packhf(v1.x, v1.y);
            s[3] = packhf(v1.z, v1.w);
        }
        __syncthreads();

#pragma unroll
        for (int kc = 0; kc < 2; kc++) {
            uint32_t af[2][4];
#pragma unroll
            for (int mt = 0; mt < 2; mt++) {
                const uint32_t* a = &As[(wm + mt * 16 + gr) * ST + kc * 8 + gc];
                af[mt][0] = a[0];
                af[mt][1] = a[8 * ST];
                af[mt][2] = a[4];
                af[mt][3] = a[8 * ST + 4];
            }
#pragma unroll
            for (int nt = 0; nt < 4; nt++) {
                const uint32_t* b = &Bs[(wn + nt * 8 + gr) * ST + kc * 8 + gc];
                uint32_t b0 = b[0], b1 = b[4];
#pragma unroll
                for (int mt = 0; mt < 2; mt++)
                    mma_f16(acc[mt][nt], af[mt], b0, b1);
            }
        }
        __syncthreads();
    }

#pragma unroll
    for (int mt = 0; mt < 2; mt++) {
#pragma unroll
        for (int nt = 0; nt < 4; nt++) {
            const int col = bn + wn + nt * 8 + gc * 2;
            float bx = 0.f, by = 0.f;
            if (EPI >= 1) { bx = bias[col]; by = bias[col + 1]; }
#pragma unroll
            for (int half = 0; half < 2; half++) {
                const int row = bm + wm + mt * 16 + gr + half * 8;
                float v0 = acc[mt][nt][half * 2 + 0];
                float v1 = acc[mt][nt][half * 2 + 1];
                if (EPI >= 1) { v0 += bx; v1 += by; }
                if (EPI == 2) { v0 = fmaxf(v0, 0.f); v1 = fmaxf(v1, 0.f); }
                if (OUTHF) {
                    __half* C = (__half*)Cv;
                    *reinterpret_cast<uint32_t*>(&C[(size_t)row * ldc + col]) = packhf(v0, v1);
                } else {
                    float* C = (float*)Cv;
                    *reinterpret_cast<float2*>(&C[(size_t)row * ldc + col]) = make_float2(v0, v1);
                }
            }
        }
    }
}

// ---------------- fused flash attention: fp16-acc QK^T, shift-free softmax ----------------
// Scores |S| << 1 -> fp16 accumulation safe for QK^T; scale folded into Q fragments.
__device__ __forceinline__ void kv_prefetch(const __half* __restrict__ qkvh,
                                            int h, int t, uint32_t stage, int tid) {
    const int r16 = tid >> 3;
    const int c8 = tid & 7;
#pragma unroll
    for (int p = 0; p < 8; p++) {
        int row = p * 16 + r16;
        const __half* base =
            qkvh + (size_t)(t * FBN_ + row) * (3 * HID_) + h * DH_ + c8 * 8;
        uint32_t d = stage + (row * KST_ + c8 * 4) * 4;
        cp16(d, base + HID_);              // K
        cp16(d + TILEB_, base + 2 * HID_); // V
    }
}

__global__ void __launch_bounds__(128) flash_attn(
    const __half* __restrict__ qkvh, __half* __restrict__ attn)
{
    extern __shared__ __align__(128) uint8_t smraw[];
    const uint32_t sbase = (uint32_t)__cvta_generic_to_shared(smraw);

    const int h = blockIdx.y;
    const int q0 = blockIdx.x * FBM_;
    const int tid = threadIdx.x;
    const int lane = tid & 31;
    const int warp = tid >> 5;
    const int gr = lane >> 2;
    const int gc = lane & 3;
    const int mhi = lane >> 3;
    const int r8 = lane & 7;
    const int wrow = warp * 16;
    const float c2 = 0.125f * LOG2E_;

    // ---- Q fragments (fp16, softmax scale pre-folded) ----
    uint32_t qf[4][4];
    {
        const uint32_t c2h2 = packhf(c2, c2);
        const uint32_t* q0p = reinterpret_cast<const uint32_t*>(
            qkvh + (size_t)(q0 + wrow + gr) * (3 * HID_) + h * DH_);
        const uint32_t* q1p = reinterpret_cast<const uint32_t*>(
            qkvh + (size_t)(q0 + wrow + gr + 8) * (3 * HID_) + h * DH_);
#pragma unroll
        for (int kc = 0; kc < 4; kc++) {
            qf[kc][0] = hmul2u(q0p[kc * 8 + gc], c2h2);
            qf[kc][1] = hmul2u(q1p[kc * 8 + gc], c2h2);
            qf[kc][2] = hmul2u(q0p[kc * 8 + gc + 4], c2h2);
            qf[kc][3] = hmul2u(q1p[kc * 8 + gc + 4], c2h2);
        }
    }

    float o[8][4];
#pragma unroll
    for (int nt = 0; nt < 8; nt++)
#pragma unroll
        for (int q = 0; q < 4; q++) o[nt][q] = 0.f;
    float l0 = 0.f, l1 = 0.f;

    kv_prefetch(qkvh, h, 0, sbase, tid);
    asm volatile("cp.async.commit_group;");

    for (int t = 0; t < NT_; t++) {
        if (t + 1 < NT_)
            kv_prefetch(qkvh, h, t + 1, sbase + ((t + 1) & 1) * STAGEB_, tid);
        asm volatile("cp.async.commit_group;");
        asm volatile("cp.async.wait_group 1;");
        __syncthreads();

        const uint32_t sK = sbase + (t & 1) * STAGEB_;
        const uint32_t sV = sK + TILEB_;

        // ---- S' = (c2*Q) @ K^T via ldmatrix.x4, fp16 accumulators ----
        uint32_t cf[16][2];
#pragma unroll
        for (int nt = 0; nt < 16; nt++) { cf[nt][0] = 0u; cf[nt][1] = 0u; }
#pragma unroll
        for (int kc = 0; kc < 4; kc++) {
#pragma unroll
            for (int ntp = 0; ntp < 8; ntp++) {
                const int row = ntp * 16 + (mhi >> 1) * 8 + r8;
                const uint32_t addr = sK + (row * KST_ + kc * 8 + (mhi & 1) * 4) * 4;
                uint32_t b0, b1, b2, b3;
                ldsm4(b0, b1, b2, b3, addr);
                mma_h16(cf[2 * ntp], qf[kc], b0, b1);
                mma_h16(cf[2 * ntp + 1], qf[kc], b2, b3);
            }
        }

        // ---- shift-free softmax: p = exp2(s'), fp16x2 straight from accumulators ----
        uint32_t pf[8][4];
        __half2 hs0[4], hs1[4];
#pragma unroll
        for (int i = 0; i < 4; i++) {
            hs0[i] = __half2half2(__ushort_as_half(0));
            hs1[i] = __half2half2(__ushort_as_half(0));
        }
#pragma unroll
        for (int nt = 0; nt < 16; nt++) {
            uint32_t p0 = ex2h2(cf[nt][0]);   // rows gr,   cols 2gc|2gc+1
            uint32_t p1 = ex2h2(cf[nt][1]);   // rows gr+8
            hs0[nt & 3] = __hadd2(hs0[nt & 3], *reinterpret_cast<__half2*>(&p0));
            hs1[nt & 3] = __hadd2(hs1[nt & 3], *reinterpret_cast<__half2*>(&p1));
            if ((nt & 1) == 0) {
                pf[nt >> 1][0] = p0;
                pf[nt >> 1][1] = p1;
            } else {
                pf[nt >> 1][2] = p0;
                pf[nt >> 1][3] = p1;
            }
        }
        float sum0 = 0.f, sum1 = 0.f;
#pragma unroll
        for (int i = 0; i < 4; i++) {
            float2 a = __half22float2(hs0[i]);
            float2 b = __half22float2(hs1[i]);
            sum0 += a.x + a.y;
            sum1 += b.x + b.y;
        }
        l0 += sum0;
        l1 += sum1;

        // ---- O += P @ V via ldmatrix.x4.trans (fp32 accumulators) ----
#pragma unroll
        for (int kt = 0; kt < 8; kt++) {
#pragma unroll
            for (int np = 0; np < 4; np++) {
                const int row = kt * 16 + (mhi & 1) * 8 + r8;
                const uint32_t addr = sV + (row * KST_ + np * 8 + (mhi >> 1) * 4) * 4;
                uint32_t v0, v1, v2, v3;
                ldsm4t(v0, v1, v2, v3, addr);
                mma_f16(o[2 * np], pf[kt], v0, v1);
                mma_f16(o[2 * np + 1], pf[kt], v2, v3);
            }
        }
        __syncthreads();
    }

    // ---- cross-quad sum of l, then epilogue: O / l -> attn (fp16) ----
    l0 += __shfl_xor_sync(0xffffffffu, l0, 1);
    l0 += __shfl_xor_sync(0xffffffffu, l0, 2);
    l1 += __shfl_xor_sync(0xffffffffu, l1, 1);
    l1 += __shfl_xor_sync(0xffffffffu, l1, 2);
    float inv0 = 1.f / l0;
    float inv1 = 1.f / l1;
    __half* obase = attn + (size_t)(q0 + wrow) * HID_ + h * DH_;
#pragma unroll
    for (int nt = 0; nt < 8; nt++) {
        int col = nt * 8 + 2 * gc;
        *reinterpret_cast<uint32_t*>(obase + (size_t)gr * HID_ + col) =
            packhf(o[nt][0] * inv0, o[nt][1] * inv0);
        *reinterpret_cast<uint32_t*>(obase + (size_t)(gr + 8) * HID_ + col) =
            packhf(o[nt][2] * inv1, o[nt][3] * inv1);
    }
}

// ---------------- GCN aggregation (CSR gather, float4, 4-way unroll) ----------------
__global__ void gcn_aggregate4(const float4* __restrict__ h4, const float* __restrict__ bias,
                               float4* __restrict__ out4, int dout4, int act)
{
    int c = blockIdx.x;
    int f = threadIdx.x;
    float dv = g_dinv[c];
    float s = dv * dv;
    float4 acc = h4[(size_t)c * dout4 + f];
    acc.x *= s; acc.y *= s; acc.z *= s; acc.w *= s;
    int e0 = g_rowptr[c], e1 = g_rowptr[c + 1];
    int e = e0;
    for (; e + 4 <= e1; e += 4) {
        int s0 = g_src[e], s1 = g_src[e + 1], s2 = g_src[e + 2], s3 = g_src[e + 3];
        float w0 = g_w[e], w1 = g_w[e + 1], w2 = g_w[e + 2], w3 = g_w[e + 3];
        float4 v0 = h4[(size_t)s0 * dout4 + f];
        float4 v1 = h4[(size_t)s1 * dout4 + f];
        float4 v2 = h4[(size_t)s2 * dout4 + f];
        float4 v3 = h4[(size_t)s3 * dout4 + f];
        acc.x += w0 * v0.x + w1 * v1.x + w2 * v2.x + w3 * v3.x;
        acc.y += w0 * v0.y + w1 * v1.y + w2 * v2.y + w3 * v3.y;
        acc.z += w0 * v0.z + w1 * v1.z + w2 * v2.z + w3 * v3.z;
        acc.w += w0 * v0.w + w1 * v1.w + w2 * v2.w + w3 * v3.w;
    }
    for (; e < e1; e++) {
        int s0 = g_src[e];
        float w0 = g_w[e];
        float4 v0 = h4[(size_t)s0 * dout4 + f];
        acc.x += w0 * v0.x; acc.y += w0 * v0.y;
        acc.z += w0 * v0.z; acc.w += w0 * v0.w;
    }
    const float4 b4 = *reinterpret_cast<const float4*>(bias + f * 4);
    acc.x += b4.x; acc.y += b4.y; acc.z += b4.z; acc.w += b4.w;
    if (act) {
        acc.x = 1.f / (1.f + __expf(-acc.x));
        acc.y = 1.f / (1.f + __expf(-acc.y));
        acc.z = 1.f / (1.f + __expf(-acc.z));
        acc.w = 1.f / (1.f + __expf(-acc.w));
    }
    out4[(size_t)c * dout4 + f] = acc;
}

// ---------------- host orchestration ----------------
static void run_mha(const float* x, float* outbuf,
                    const float* ipw, const float* ipb,
                    const float* opw, const float* opb,
                    __half* qkvh, __half* attnh)
{
    tc_gemm<1, 1, 0><<<dim3(12, 32), 256>>>(
        x, HID_, ipw, HID_, ipb, qkvh, 3 * HID_, HID_);

    flash_attn<<<dim3(L_ / FBM_, HEADS_), 128, 2 * STAGEB_>>>(qkvh, attnh);

    tc_gemm<2, 0, 1><<<dim3(4, 32), 256>>>(
        attnh, HID_, opw, HID_, opb, outbuf, HID_, HID_);
}

extern "C" void kernel_launch(void* const* d_in, const int* in_sizes, int n_in,
                              void* d_out, int out_size)
{
    const float* x_in = (const float*)d_in[0];
    const int*   ei   = (const int*)d_in[1];
    const float* ew   = (const float*)d_in[2];
    const float* W1   = (const float*)d_in[3];
    const float* b1   = (const float*)d_in[4];
    const float* W2   = (const float*)d_in[5];
    const float* b2   = (const float*)d_in[6];
    const float* W3   = (const float*)d_in[7];
    const float* b3   = (const float*)d_in[8];
    const float* ipw  = (const float*)d_in[9];
    const float* ipb  = (const float*)d_in[10];
    const float* opw  = (const float*)d_in[11];
    const float* opb  = (const float*)d_in[12];
    float* out = (float*)d_out;

    float *ph, *pa, *pb, *pw1t, *pw2t, *pw3t;
    __half *pqkvh, *pattnh;
    cudaGetSymbolAddress((void**)&ph, g_h);
    cudaGetSymbolAddress((void**)&pa, g_a);
    cudaGetSymbolAddress((void**)&pb, g_b);
    cudaGetSymbolAddress((void**)&pattnh, g_attnh);
    cudaGetSymbolAddress((void**)&pqkvh, g_qkvh);
    cudaGetSymbolAddress((void**)&pw1t, g_w1t);
    cudaGetSymbolAddress((void**)&pw2t, g_w2t);
    cudaGetSymbolAddress((void**)&pw3t, g_w3t);

    static cudaStream_t s2 = nullptr;
    static cudaEvent_t evFork = nullptr, evJoin = nullptr;
    if (s2 == nullptr) {
        cudaStreamCreateWithFlags(&s2, cudaStreamNonBlocking);
        cudaEventCreateWithFlags(&evFork, cudaEventDisableTiming);
        cudaEventCreateWithFlags(&evJoin, cudaEventDisableTiming);
        cudaFuncSetAttribute(flash_attn, cudaFuncAttributeMaxDynamicSharedMemorySize,
                             2 * STAGEB_);
    }

    // ---- fork: preproc chain on s2 || transposes + layer-1 GEMM on main stream ----
    cudaEventRecord(evFork, 0);
    cudaStreamWaitEvent(s2, evFork, 0);

    k_init<<<NN_ / 256, 256, 0, s2>>>();
    k_deg<<<EE_ / 256, 256, 0, s2>>>(ei, ew);
    k_dinv<<<NN_ / 256, 256, 0, s2>>>();
    k_scan<<<1, 256, 0, s2>>>();
    k_fill<<<EE_ / 256, 256, 0, s2>>>(ei, ew);
    cudaEventRecord(evJoin, s2);

    k_transpose3<<<dim3(8, 8, 3), dim3(32, 8)>>>(W1, pw1t, W2, pw2t, W3, pw3t);
    tc_gemm<0, 0, 0><<<dim3(HID_ / 64, NN_ / 128), 256>>>(
        x_in, 256, pw1t, 256, nullptr, ph, HID_, 256);

    cudaStreamWaitEvent(0, evJoin, 0);

    // --- layer 1: gcn aggregate ---
    gcn_aggregate4<<<NN_, HID_ / 4>>>((const float4*)ph, b1, (float4*)pa, HID_ / 4, 0);

    // --- mha 1 (with relu) ---
    run_mha(pa, pb, ipw, ipb, opw, opb, pqkvh, pattnh);

    // --- layer 2: gcn ---
    tc_gemm<0, 0, 0><<<dim3(HID_ / 64, NN_ / 128), 256>>>(
        pb, HID_, pw2t, HID_, nullptr, ph, HID_, HID_);
    gcn_aggregate4<<<NN_, HID_ / 4>>>((const float4*)ph, b2, (float4*)pa, HID_ / 4, 0);

    // --- mha 2 (with relu) ---
    run_mha(pa, pb, ipw, ipb, opw, opb, pqkvh, pattnh);

    // --- layer 3: gcn + sigmoid -> d_out ---
    tc_gemm<0, 0, 0><<<dim3(DOUT_ / 64, NN_ / 128), 256>>>(
        pb, HID_, pw3t, HID_, nullptr, ph, DOUT_, HID_);
    gcn_aggregate4<<<NN_, DOUT_ / 4>>>((const float4*)ph, b3, (float4*)out, DOUT_ / 4, 1);
}

// round 16
// speedup vs baseline: 1.0590x; 1.0590x over previous
#include <cuda_runtime.h>
#include <cuda_fp16.h>
#include <math.h>
#include <stdint.h>

#define NN_ 4096
#define EE_ 262144
#define HID_ 256
#define DOUT_ 128
#define HEADS_ 4
#define DH_ 64
#define L_ 4096
#define FBM_ 64
#define FBN_ 128
#define NT_ (L_ / FBN_)
#define KST_ 36
#define TILEB_ (128 * KST_ * 4)
#define STAGEB_ (2 * TILEB_)
#define LOG2E_ 1.4426950408889634f

// ---------------- scratch (all static __device__, no allocations) ----------------
__device__ float g_deg[NN_];
__device__ float g_dinv[NN_];
__device__ int   g_cnt[NN_];
__device__ int   g_rowptr[NN_ + 1];
__device__ int   g_fill[NN_];
__device__ int   g_src[EE_];
__device__ float g_w[EE_];

__device__ float g_h[NN_ * HID_];
__device__ __half g_ah[NN_ * HID_];     // gcn output -> mha input (fp16)
__device__ __half g_bh[NN_ * HID_];     // mha output -> gcn GEMM input (fp16)
__device__ __half g_attnh[NN_ * HID_];
__device__ __half g_qkvh[NN_ * 3 * HID_];
__device__ float g_w1t[HID_ * 256];
__device__ float g_w2t[HID_ * HID_];
__device__ float g_w3t[DOUT_ * HID_];

// ---------------- preprocessing ----------------
__global__ void k_init() {
    int i = blockIdx.x * blockDim.x + threadIdx.x;
    if (i < NN_) { g_deg[i] = 1.0f; g_cnt[i] = 0; }
}

__global__ void k_deg(const int* __restrict__ ei, const float* __restrict__ ew) {
    int e = blockIdx.x * blockDim.x + threadIdx.x;
    if (e < EE_) {
        int c = ei[EE_ + e];
        atomicAdd(&g_deg[c], ew[e]);
        atomicAdd(&g_cnt[c], 1);
    }
}

__global__ void k_dinv() {
    int i = blockIdx.x * blockDim.x + threadIdx.x;
    if (i < NN_) {
        float d = g_deg[i];
        g_dinv[i] = (d > 0.f) ? rsqrtf(d) : 0.f;
    }
}

// warp-shuffle exclusive scan of g_cnt (4096) -> g_rowptr / g_fill. 256 threads.
__global__ void k_scan() {
    __shared__ int wsum[8];
    int t = threadIdx.x;
    int lane = t & 31, w = t >> 5;
    int base = t * 16;
    int v[16], s = 0;
#pragma unroll
    for (int i = 0; i < 16; i++) { v[i] = g_cnt[base + i]; s += v[i]; }
    int run = s;
#pragma unroll
    for (int off = 1; off < 32; off <<= 1) {
        int x = __shfl_up_sync(0xffffffffu, run, off);
        if (lane >= off) run += x;
    }
    if (lane == 31) wsum[w] = run;
    __syncthreads();
    if (w == 0) {
        int x = (lane < 8) ? wsum[lane] : 0;
#pragma unroll
        for (int off = 1; off < 8; off <<= 1) {
            int y = __shfl_up_sync(0xffffffffu, x, off);
            if (lane >= off) x += y;
        }
        if (lane < 8) wsum[lane] = x;
    }
    __syncthreads();
    int excl = run - s + (w ? wsum[w - 1] : 0);
#pragma unroll
    for (int i = 0; i < 16; i++) {
        g_rowptr[base + i] = excl;
        g_fill[base + i] = excl;
        excl += v[i];
    }
    if (t == 255) g_rowptr[NN_] = excl;
}

__global__ void k_fill(const int* __restrict__ ei, const float* __restrict__ ew) {
    int e = blockIdx.x * blockDim.x + threadIdx.x;
    if (e < EE_) {
        int r = ei[e];
        int c = ei[EE_ + e];
        int pos = atomicAdd(&g_fill[c], 1);
        g_src[pos] = r;
        g_w[pos] = g_dinv[r] * ew[e] * g_dinv[c];
    }
}

// Three transposes in one launch: z=0 W1[256,256], z=1 W2[256,256], z=2 W3[256,128]
__global__ void k_transpose3(const float* __restrict__ W1, float* __restrict__ W1T,
                             const float* __restrict__ W2, float* __restrict__ W2T,
                             const float* __restrict__ W3, float* __restrict__ W3T) {
    __shared__ float tile[32][33];
    const float* W;
    float* WT;
    int R, C;
    if (blockIdx.z == 0)      { W = W1; WT = W1T; R = 256; C = HID_; }
    else if (blockIdx.z == 1) { W = W2; WT = W2T; R = HID_; C = HID_; }
    else                      { W = W3; WT = W3T; R = HID_; C = DOUT_; }
    int c0 = blockIdx.x * 32, r0 = blockIdx.y * 32;
    if (c0 >= C || r0 >= R) return;
    for (int i = threadIdx.y; i < 32; i += 8)
        tile[i][threadIdx.x] = W[(size_t)(r0 + i) * C + c0 + threadIdx.x];
    __syncthreads();
    for (int i = threadIdx.y; i < 32; i += 8)
        WT[(size_t)(c0 + i) * R + r0 + threadIdx.x] = tile[threadIdx.x][i];
}

// ---------------- fp16 / mma helpers ----------------
__device__ __forceinline__ uint32_t packhf(float lo, float hi) {
    uint32_t u;
    asm("cvt.rn.f16x2.f32 %0, %1, %2;" : "=r"(u) : "f"(hi), "f"(lo));
    return u;
}

__device__ __forceinline__ uint32_t ex2h2(uint32_t x) {
    uint32_t y;
    asm("ex2.approx.f16x2 %0, %1;" : "=r"(y) : "r"(x));
    return y;
}

__device__ __forceinline__ void mma_f16(float c[4], const uint32_t a[4], uint32_t b0, uint32_t b1) {
    asm volatile(
        "mma.sync.aligned.m16n8k16.row.col.f32.f16.f16.f32 "
        "{%0,%1,%2,%3}, {%4,%5,%6,%7}, {%8,%9}, {%0,%1,%2,%3};"
        : "+f"(c[0]), "+f"(c[1]), "+f"(c[2]), "+f"(c[3])
        : "r"(a[0]), "r"(a[1]), "r"(a[2]), "r"(a[3]), "r"(b0), "r"(b1));
}

__device__ __forceinline__ void ldsm4(uint32_t& r0, uint32_t& r1, uint32_t& r2, uint32_t& r3,
                                      uint32_t addr) {
    asm volatile("ldmatrix.sync.aligned.m8n8.x4.shared.b16 {%0,%1,%2,%3}, [%4];"
                 : "=r"(r0), "=r"(r1), "=r"(r2), "=r"(r3) : "r"(addr));
}

__device__ __forceinline__ void ldsm4t(uint32_t& r0, uint32_t& r1, uint32_t& r2, uint32_t& r3,
                                       uint32_t addr) {
    asm volatile("ldmatrix.sync.aligned.m8n8.x4.trans.shared.b16 {%0,%1,%2,%3}, [%4];"
                 : "=r"(r0), "=r"(r1), "=r"(r2), "=r"(r3) : "r"(addr));
}

__device__ __forceinline__ void cp16(uint32_t dst, const void* src) {
    asm volatile("cp.async.ca.shared.global [%0], [%1], 16;" :: "r"(dst), "l"(src));
}

// ---------------- fp16 tensor-core GEMM:  C = A @ B^T (+bias)(+relu) ----------------
// AHF=1: A is fp16 [M,K] (raw copy staging, 16 halves = 2x uint4 per thread).
// AHF=0: A fp32 (cvt on staging).
template <int EPI, int OUTHF, int AHF>
__global__ void __launch_bounds__(256) tc_gemm(
    const void* __restrict__ Av, int lda,
    const float* __restrict__ B, int ldb,
    const float* __restrict__ bias,
    void* __restrict__ Cv, int ldc, int K)
{
    constexpr int BM = 128, BN = 64, BK = 32, ST = 20;
    __shared__ uint32_t As[BM * ST];
    __shared__ uint32_t Bs[BN * ST];

    const int bm = blockIdx.y * BM;
    const int bn = blockIdx.x * BN;
    const int tid = threadIdx.x;
    const int lane = tid & 31;
    const int warp = tid >> 5;
    const int wm = (warp & 3) * 32;
    const int wn = (warp >> 2) * 32;
    const int gr = lane >> 2;
    const int gc = lane & 3;

    float acc[2][4][4];
#pragma unroll
    for (int mt = 0; mt < 2; mt++)
#pragma unroll
        for (int nt = 0; nt < 4; nt++)
#pragma unroll
            for (int q = 0; q < 4; q++) acc[mt][nt][q] = 0.f;

    for (int kt = 0; kt < K; kt += BK) {
        if (AHF) {
            const __half* A = (const __half*)Av;
            const int m = tid >> 1;
            const int kh = (tid & 1) * 16;
            const __half* p = A + (size_t)(bm + m) * lda + kt + kh;
            const uint4 v0 = *reinterpret_cast<const uint4*>(p);
            const uint4 v1 = *reinterpret_cast<const uint4*>(p + 8);
            uint32_t* s = &As[m * ST + kh / 2];
            s[0] = v0.x; s[1] = v0.y; s[2] = v0.z; s[3] = v0.w;
            s[4] = v1.x; s[5] = v1.y; s[6] = v1.z; s[7] = v1.w;
        } else {
            const float* A = (const float*)Av;
            const int m = tid >> 1;
            const int kh = (tid & 1) * 16;
            const float* p = A + (size_t)(bm + m) * lda + kt + kh;
            uint32_t* s = &As[m * ST + kh / 2];
#pragma unroll
            for (int j = 0; j < 4; j++) {
                float4 v = *reinterpret_cast<const float4*>(p + j * 4);
                s[j * 2 + 0] = packhf(v.x, v.y);
                s[j * 2 + 1] = packhf(v.z, v.w);
            }
        }
        {
            const int n = tid >> 2;
            const int kh = (tid & 3) * 8;
            const float* p = B + (size_t)(bn + n) * ldb + kt + kh;
            uint32_t* s = &Bs[n * ST + kh / 2];
            float4 v0 = *reinterpret_cast<const float4*>(p);
            float4 v1 = *reinterpret_cast<const float4*>(p + 4);
            s[0] = packhf(v0.x, v0.y);
            s[1] = packhf(v0.z, v0.w);
            s[2] = packhf(v1.x, v1.y);
            s[3] = packhf(v1.z, v1.w);
        }
        __syncthreads();

#pragma unroll
        for (int kc = 0; kc < 2; kc++) {
            uint32_t af[2][4];
#pragma unroll
            for (int mt = 0; mt < 2; mt++) {
                const uint32_t* a = &As[(wm + mt * 16 + gr) * ST + kc * 8 + gc];
                af[mt][0] = a[0];
                af[mt][1] = a[8 * ST];
                af[mt][2] = a[4];
                af[mt][3] = a[8 * ST + 4];
            }
#pragma unroll
            for (int nt = 0; nt < 4; nt++) {
                const uint32_t* b = &Bs[(wn + nt * 8 + gr) * ST + kc * 8 + gc];
                uint32_t b0 = b[0], b1 = b[4];
#pragma unroll
                for (int mt = 0; mt < 2; mt++)
                    mma_f16(acc[mt][nt], af[mt], b0, b1);
            }
        }
        __syncthreads();
    }

#pragma unroll
    for (int mt = 0; mt < 2; mt++) {
#pragma unroll
        for (int nt = 0; nt < 4; nt++) {
            const int col = bn + wn + nt * 8 + gc * 2;
            float bx = 0.f, by = 0.f;
            if (EPI >= 1) { bx = bias[col]; by = bias[col + 1]; }
#pragma unroll
            for (int half = 0; half < 2; half++) {
                const int row = bm + wm + mt * 16 + gr + half * 8;
                float v0 = acc[mt][nt][half * 2 + 0];
                float v1 = acc[mt][nt][half * 2 + 1];
                if (EPI >= 1) { v0 += bx; v1 += by; }
                if (EPI == 2) { v0 = fmaxf(v0, 0.f); v1 = fmaxf(v1, 0.f); }
                if (OUTHF) {
                    __half* C = (__half*)Cv;
                    *reinterpret_cast<uint32_t*>(&C[(size_t)row * ldc + col]) = packhf(v0, v1);
                } else {
                    float* C = (float*)Cv;
                    *reinterpret_cast<float2*>(&C[(size_t)row * ldc + col]) = make_float2(v0, v1);
                }
            }
        }
    }
}

// ---------------- fused flash attention: fp16 mma, shift-free softmax ----------------
__device__ __forceinline__ void kv_prefetch(const __half* __restrict__ qkvh,
                                            int h, int t, uint32_t stage, int tid) {
    const int r16 = tid >> 3;
    const int c8 = tid & 7;
#pragma unroll
    for (int p = 0; p < 8; p++) {
        int row = p * 16 + r16;
        const __half* base =
            qkvh + (size_t)(t * FBN_ + row) * (3 * HID_) + h * DH_ + c8 * 8;
        uint32_t d = stage + (row * KST_ + c8 * 4) * 4;
        cp16(d, base + HID_);              // K
        cp16(d + TILEB_, base + 2 * HID_); // V
    }
}

__global__ void __launch_bounds__(128) flash_attn(
    const __half* __restrict__ qkvh, __half* __restrict__ attn)
{
    extern __shared__ __align__(128) uint8_t smraw[];
    const uint32_t sbase = (uint32_t)__cvta_generic_to_shared(smraw);

    const int h = blockIdx.y;
    const int q0 = blockIdx.x * FBM_;
    const int tid = threadIdx.x;
    const int lane = tid & 31;
    const int warp = tid >> 5;
    const int gr = lane >> 2;
    const int gc = lane & 3;
    const int mhi = lane >> 3;
    const int r8 = lane & 7;
    const int wrow = warp * 16;
    const float c2 = 0.125f * LOG2E_;

    // ---- Q fragments (raw fp16) ----
    uint32_t qf[4][4];
    {
        const uint32_t* q0p = reinterpret_cast<const uint32_t*>(
            qkvh + (size_t)(q0 + wrow + gr) * (3 * HID_) + h * DH_);
        const uint32_t* q1p = reinterpret_cast<const uint32_t*>(
            qkvh + (size_t)(q0 + wrow + gr + 8) * (3 * HID_) + h * DH_);
#pragma unroll
        for (int kc = 0; kc < 4; kc++) {
            qf[kc][0] = q0p[kc * 8 + gc];
            qf[kc][1] = q1p[kc * 8 + gc];
            qf[kc][2] = q0p[kc * 8 + gc + 4];
            qf[kc][3] = q1p[kc * 8 + gc + 4];
        }
    }

    float o[8][4];
#pragma unroll
    for (int nt = 0; nt < 8; nt++)
#pragma unroll
        for (int q = 0; q < 4; q++) o[nt][q] = 0.f;
    float l0 = 0.f, l1 = 0.f;

    kv_prefetch(qkvh, h, 0, sbase, tid);
    asm volatile("cp.async.commit_group;");

    for (int t = 0; t < NT_; t++) {
        if (t + 1 < NT_)
            kv_prefetch(qkvh, h, t + 1, sbase + ((t + 1) & 1) * STAGEB_, tid);
        asm volatile("cp.async.commit_group;");
        asm volatile("cp.async.wait_group 1;");
        __syncthreads();

        const uint32_t sK = sbase + (t & 1) * STAGEB_;
        const uint32_t sV = sK + TILEB_;

        // ---- S = Q @ K^T via ldmatrix.x4 ----
        float cf[16][4];
#pragma unroll
        for (int nt = 0; nt < 16; nt++)
#pragma unroll
            for (int q = 0; q < 4; q++) cf[nt][q] = 0.f;
#pragma unroll
        for (int kc = 0; kc < 4; kc++) {
#pragma unroll
            for (int ntp = 0; ntp < 8; ntp++) {
                const int row = ntp * 16 + (mhi >> 1) * 8 + r8;
                const uint32_t addr = sK + (row * KST_ + kc * 8 + (mhi & 1) * 4) * 4;
                uint32_t b0, b1, b2, b3;
                ldsm4(b0, b1, b2, b3, addr);
                mma_f16(cf[2 * ntp], qf[kc], b0, b1);
                mma_f16(cf[2 * ntp + 1], qf[kc], b2, b3);
            }
        }

        // ---- shift-free softmax: p = exp2(c2 * s), fp16x2 ----
        uint32_t pf[8][4];
        __half2 hs0[4], hs1[4];
#pragma unroll
        for (int i = 0; i < 4; i++) {
            hs0[i] = __half2half2(__ushort_as_half(0));
            hs1[i] = __half2half2(__ushort_as_half(0));
        }
#pragma unroll
        for (int nt = 0; nt < 16; nt++) {
            uint32_t p0 = ex2h2(packhf(c2 * cf[nt][0], c2 * cf[nt][1]));
            uint32_t p1 = ex2h2(packhf(c2 * cf[nt][2], c2 * cf[nt][3]));
            hs0[nt & 3] = __hadd2(hs0[nt & 3], *reinterpret_cast<__half2*>(&p0));
            hs1[nt & 3] = __hadd2(hs1[nt & 3], *reinterpret_cast<__half2*>(&p1));
            if ((nt & 1) == 0) {
                pf[nt >> 1][0] = p0;
                pf[nt >> 1][1] = p1;
            } else {
                pf[nt >> 1][2] = p0;
                pf[nt >> 1][3] = p1;
            }
        }
        float sum0 = 0.f, sum1 = 0.f;
#pragma unroll
        for (int i = 0; i < 4; i++) {
            float2 a = __half22float2(hs0[i]);
            float2 b = __half22float2(hs1[i]);
            sum0 += a.x + a.y;
            sum1 += b.x + b.y;
        }
        l0 += sum0;
        l1 += sum1;

        // ---- O += P @ V via ldmatrix.x4.trans ----
#pragma unroll
        for (int kt = 0; kt < 8; kt++) {
#pragma unroll
            for (int np = 0; np < 4; np++) {
                const int row = kt * 16 + (mhi & 1) * 8 + r8;
                const uint32_t addr = sV + (row * KST_ + np * 8 + (mhi >> 1) * 4) * 4;
                uint32_t v0, v1, v2, v3;
                ldsm4t(v0, v1, v2, v3, addr);
                mma_f16(o[2 * np], pf[kt], v0, v1);
                mma_f16(o[2 * np + 1], pf[kt], v2, v3);
            }
        }
        __syncthreads();
    }

    // ---- cross-quad sum of l, then epilogue: O / l -> attn (fp16) ----
    l0 += __shfl_xor_sync(0xffffffffu, l0, 1);
    l0 += __shfl_xor_sync(0xffffffffu, l0, 2);
    l1 += __shfl_xor_sync(0xffffffffu, l1, 1);
    l1 += __shfl_xor_sync(0xffffffffu, l1, 2);
    float inv0 = 1.f / l0;
    float inv1 = 1.f / l1;
    __half* obase = attn + (size_t)(q0 + wrow) * HID_ + h * DH_;
#pragma unroll
    for (int nt = 0; nt < 8; nt++) {
        int col = nt * 8 + 2 * gc;
        *reinterpret_cast<uint32_t*>(obase + (size_t)gr * HID_ + col) =
            packhf(o[nt][0] * inv0, o[nt][1] * inv0);
        *reinterpret_cast<uint32_t*>(obase + (size_t)(gr + 8) * HID_ + col) =
            packhf(o[nt][2] * inv1, o[nt][3] * inv1);
    }
}

// ---------------- GCN aggregation (CSR gather, float4, 4-way unroll) ----------------
// OUTHF=1: write packed fp16 (uint2). OUTHF=0: write float4 (with optional sigmoid).
template <int OUTHF>
__global__ void gcn_aggregate4(const float4* __restrict__ h4, const float* __restrict__ bias,
                               void* __restrict__ outv, int dout4, int act)
{
    int c = blockIdx.x;
    int f = threadIdx.x;
    float dv = g_dinv[c];
    float s = dv * dv;
    float4 acc = h4[(size_t)c * dout4 + f];
    acc.x *= s; acc.y *= s; acc.z *= s; acc.w *= s;
    int e0 = g_rowptr[c], e1 = g_rowptr[c + 1];
    int e = e0;
    for (; e + 4 <= e1; e += 4) {
        int s0 = g_src[e], s1 = g_src[e + 1], s2 = g_src[e + 2], s3 = g_src[e + 3];
        float w0 = g_w[e], w1 = g_w[e + 1], w2 = g_w[e + 2], w3 = g_w[e + 3];
        float4 v0 = h4[(size_t)s0 * dout4 + f];
        float4 v1 = h4[(size_t)s1 * dout4 + f];
        float4 v2 = h4[(size_t)s2 * dout4 + f];
        float4 v3 = h4[(size_t)s3 * dout4 + f];
        acc.x += w0 * v0.x + w1 * v1.x + w2 * v2.x + w3 * v3.x;
        acc.y += w0 * v0.y + w1 * v1.y + w2 * v2.y + w3 * v3.y;
        acc.z += w0 * v0.z + w1 * v1.z + w2 * v2.z + w3 * v3.z;
        acc.w += w0 * v0.w + w1 * v1.w + w2 * v2.w + w3 * v3.w;
    }
    for (; e < e1; e++) {
        int s0 = g_src[e];
        float w0 = g_w[e];
        float4 v0 = h4[(size_t)s0 * dout4 + f];
        acc.x += w0 * v0.x; acc.y += w0 * v0.y;
        acc.z += w0 * v0.z; acc.w += w0 * v0.w;
    }
    const float4 b4 = *reinterpret_cast<const float4*>(bias + f * 4);
    acc.x += b4.x; acc.y += b4.y; acc.z += b4.z; acc.w += b4.w;
    if (act) {
        acc.x = 1.f / (1.f + __expf(-acc.x));
        acc.y = 1.f / (1.f + __expf(-acc.y));
        acc.z = 1.f / (1.f + __expf(-acc.z));
        acc.w = 1.f / (1.f + __expf(-acc.w));
    }
    if (OUTHF) {
        uint2 o;
        o.x = packhf(acc.x, acc.y);
        o.y = packhf(acc.z, acc.w);
        reinterpret_cast<uint2*>(outv)[(size_t)c * dout4 + f] = o;
    } else {
        reinterpret_cast<float4*>(outv)[(size_t)c * dout4 + f] = acc;
    }
}

// ---------------- host orchestration ----------------
static void run_mha(const __half* xh, __half* outbh,
                    const float* ipw, const float* ipb,
                    const float* opw, const float* opb,
                    __half* qkvh, __half* attnh)
{
    tc_gemm<1, 1, 1><<<dim3(12, 32), 256>>>(
        xh, HID_, ipw, HID_, ipb, qkvh, 3 * HID_, HID_);

    flash_attn<<<dim3(L_ / FBM_, HEADS_), 128, 2 * STAGEB_>>>(qkvh, attnh);

    tc_gemm<2, 1, 1><<<dim3(4, 32), 256>>>(
        attnh, HID_, opw, HID_, opb, outbh, HID_, HID_);
}

extern "C" void kernel_launch(void* const* d_in, const int* in_sizes, int n_in,
                              void* d_out, int out_size)
{
    const float* x_in = (const float*)d_in[0];
    const int*   ei   = (const int*)d_in[1];
    const float* ew   = (const float*)d_in[2];
    const float* W1   = (const float*)d_in[3];
    const float* b1   = (const float*)d_in[4];
    const float* W2   = (const float*)d_in[5];
    const float* b2   = (const float*)d_in[6];
    const float* W3   = (const float*)d_in[7];
    const float* b3   = (const float*)d_in[8];
    const float* ipw  = (const float*)d_in[9];
    const float* ipb  = (const float*)d_in[10];
    const float* opw  = (const float*)d_in[11];
    const float* opb  = (const float*)d_in[12];
    float* out = (float*)d_out;

    float *ph, *pw1t, *pw2t, *pw3t;
    __half *pqkvh, *pattnh, *pah, *pbh;
    cudaGetSymbolAddress((void**)&ph, g_h);
    cudaGetSymbolAddress((void**)&pah, g_ah);
    cudaGetSymbolAddress((void**)&pbh, g_bh);
    cudaGetSymbolAddress((void**)&pattnh, g_attnh);
    cudaGetSymbolAddress((void**)&pqkvh, g_qkvh);
    cudaGetSymbolAddress((void**)&pw1t, g_w1t);
    cudaGetSymbolAddress((void**)&pw2t, g_w2t);
    cudaGetSymbolAddress((void**)&pw3t, g_w3t);

    static cudaStream_t s2 = nullptr;
    static cudaEvent_t evFork = nullptr, evJoin = nullptr;
    if (s2 == nullptr) {
        cudaStreamCreateWithFlags(&s2, cudaStreamNonBlocking);
        cudaEventCreateWithFlags(&evFork, cudaEventDisableTiming);
        cudaEventCreateWithFlags(&evJoin, cudaEventDisableTiming);
        cudaFuncSetAttribute(flash_attn, cudaFuncAttributeMaxDynamicSharedMemorySize,
                             2 * STAGEB_);
    }

    // ---- fork: preproc chain on s2 || transposes + layer-1 GEMM on main stream ----
    cudaEventRecord(evFork, 0);
    cudaStreamWaitEvent(s2, evFork, 0);

    k_init<<<NN_ / 256, 256, 0, s2>>>();
    k_deg<<<EE_ / 256, 256, 0, s2>>>(ei, ew);
    k_dinv<<<NN_ / 256, 256, 0, s2>>>();
    k_scan<<<1, 256, 0, s2>>>();
    k_fill<<<EE_ / 256, 256, 0, s2>>>(ei, ew);
    cudaEventRecord(evJoin, s2);

    k_transpose3<<<dim3(8, 8, 3), dim3(32, 8)>>>(W1, pw1t, W2, pw2t, W3, pw3t);
    tc_gemm<0, 0, 0><<<dim3(HID_ / 64, NN_ / 128), 256>>>(
        x_in, 256, pw1t, 256, nullptr, ph, HID_, 256);

    cudaStreamWaitEvent(0, evJoin, 0);

    // --- layer 1: gcn aggregate (-> fp16 for mha) ---
    gcn_aggregate4<1><<<NN_, HID_ / 4>>>((const float4*)ph, b1, pah, HID_ / 4, 0);

    // --- mha 1 (with relu) ---
    run_mha(pah, pbh, ipw, ipb, opw, opb, pqkvh, pattnh);

    // --- layer 2: gcn ---
    tc_gemm<0, 0, 1><<<dim3(HID_ / 64, NN_ / 128), 256>>>(
        pbh, HID_, pw2t, HID_, nullptr, ph, HID_, HID_);
    gcn_aggregate4<1><<<NN_, HID_ / 4>>>((const float4*)ph, b2, pah, HID_ / 4, 0);

    // --- mha 2 (with relu) ---
    run_mha(pah, pbh, ipw, ipb, opw, opb, pqkvh, pattnh);

    // --- layer 3: gcn + sigmoid -> d_out (fp32) ---
    tc_gemm<0, 0, 1><<<dim3(DOUT_ / 64, NN_ / 128), 256>>>(
        pbh, HID_, pw3t, HID_, nullptr, ph, DOUT_, HID_);
    gcn_aggregate4<0><<<NN_, DOUT_ / 4>>>((const float4*)ph, b3, out, DOUT_ / 4, 1);
}

// round 17
// speedup vs baseline: 1.0792x; 1.0191x over previous
#include <cuda_runtime.h>
#include <cuda_fp16.h>
#include <math.h>
#include <stdint.h>

#define NN_ 4096
#define EE_ 262144
#define HID_ 256
#define DOUT_ 128
#define HEADS_ 4
#define DH_ 64
#define L_ 4096
#define FBM_ 64
#define FBN_ 128
#define NT_ (L_ / FBN_)
#define KST_ 36
#define TILEB_ (128 * KST_ * 4)
#define STAGEB_ (2 * TILEB_)
#define LOG2E_ 1.4426950408889634f

// ---------------- scratch (all static __device__, no allocations) ----------------
__device__ float g_deg[NN_];
__device__ float g_dinv[NN_];
__device__ int   g_cnt[NN_];
__device__ int   g_rowptr[NN_ + 1];
__device__ int   g_fill[NN_];
__device__ int   g_src[EE_];
__device__ float g_w[EE_];

__device__ float g_h[NN_ * HID_];
__device__ __half g_ah[NN_ * HID_];
__device__ __half g_bh[NN_ * HID_];
__device__ __half g_attnh[NN_ * HID_];
__device__ __half g_qkvh[NN_ * 3 * HID_];
__device__ float g_w1t[HID_ * 256];
__device__ float g_w2t[HID_ * HID_];
__device__ float g_w3t[DOUT_ * HID_];

// ---------------- preprocessing ----------------
__global__ void k_init() {
    int i = blockIdx.x * blockDim.x + threadIdx.x;
    if (i < NN_) { g_deg[i] = 1.0f; g_cnt[i] = 0; }
}

__global__ void k_deg(const int* __restrict__ ei, const float* __restrict__ ew) {
    int e = blockIdx.x * blockDim.x + threadIdx.x;
    if (e < EE_) {
        int c = ei[EE_ + e];
        atomicAdd(&g_deg[c], ew[e]);
        atomicAdd(&g_cnt[c], 1);
    }
}

__global__ void k_dinv() {
    int i = blockIdx.x * blockDim.x + threadIdx.x;
    if (i < NN_) {
        float d = g_deg[i];
        g_dinv[i] = (d > 0.f) ? rsqrtf(d) : 0.f;
    }
}

// warp-shuffle exclusive scan of g_cnt (4096) -> g_rowptr / g_fill. 256 threads.
__global__ void k_scan() {
    __shared__ int wsum[8];
    int t = threadIdx.x;
    int lane = t & 31, w = t >> 5;
    int base = t * 16;
    int v[16], s = 0;
#pragma unroll
    for (int i = 0; i < 16; i++) { v[i] = g_cnt[base + i]; s += v[i]; }
    int run = s;
#pragma unroll
    for (int off = 1; off < 32; off <<= 1) {
        int x = __shfl_up_sync(0xffffffffu, run, off);
        if (lane >= off) run += x;
    }
    if (lane == 31) wsum[w] = run;
    __syncthreads();
    if (w == 0) {
        int x = (lane < 8) ? wsum[lane] : 0;
#pragma unroll
        for (int off = 1; off < 8; off <<= 1) {
            int y = __shfl_up_sync(0xffffffffu, x, off);
            if (lane >= off) x += y;
        }
        if (lane < 8) wsum[lane] = x;
    }
    __syncthreads();
    int excl = run - s + (w ? wsum[w - 1] : 0);
#pragma unroll
    for (int i = 0; i < 16; i++) {
        g_rowptr[base + i] = excl;
        g_fill[base + i] = excl;
        excl += v[i];
    }
    if (t == 255) g_rowptr[NN_] = excl;
}

__global__ void k_fill(const int* __restrict__ ei, const float* __restrict__ ew) {
    int e = blockIdx.x * blockDim.x + threadIdx.x;
    if (e < EE_) {
        int r = ei[e];
        int c = ei[EE_ + e];
        int pos = atomicAdd(&g_fill[c], 1);
        g_src[pos] = r;
        g_w[pos] = g_dinv[r] * ew[e] * g_dinv[c];
    }
}

// Three transposes in one launch: z=0 W1[256,256], z=1 W2[256,256], z=2 W3[256,128]
__global__ void k_transpose3(const float* __restrict__ W1, float* __restrict__ W1T,
                             const float* __restrict__ W2, float* __restrict__ W2T,
                             const float* __restrict__ W3, float* __restrict__ W3T) {
    __shared__ float tile[32][33];
    const float* W;
    float* WT;
    int R, C;
    if (blockIdx.z == 0)      { W = W1; WT = W1T; R = 256; C = HID_; }
    else if (blockIdx.z == 1) { W = W2; WT = W2T; R = HID_; C = HID_; }
    else                      { W = W3; WT = W3T; R = HID_; C = DOUT_; }
    int c0 = blockIdx.x * 32, r0 = blockIdx.y * 32;
    if (c0 >= C || r0 >= R) return;
    for (int i = threadIdx.y; i < 32; i += 8)
        tile[i][threadIdx.x] = W[(size_t)(r0 + i) * C + c0 + threadIdx.x];
    __syncthreads();
    for (int i = threadIdx.y; i < 32; i += 8)
        WT[(size_t)(c0 + i) * R + r0 + threadIdx.x] = tile[threadIdx.x][i];
}

// ---------------- fp16 / mma helpers ----------------
__device__ __forceinline__ uint32_t packhf(float lo, float hi) {
    uint32_t u;
    asm("cvt.rn.f16x2.f32 %0, %1, %2;" : "=r"(u) : "f"(hi), "f"(lo));
    return u;
}

__device__ __forceinline__ uint32_t ex2h2(uint32_t x) {
    uint32_t y;
    asm("ex2.approx.f16x2 %0, %1;" : "=r"(y) : "r"(x));
    return y;
}

__device__ __forceinline__ void mma_f16(float c[4], const uint32_t a[4], uint32_t b0, uint32_t b1) {
    asm volatile(
        "mma.sync.aligned.m16n8k16.row.col.f32.f16.f16.f32 "
        "{%0,%1,%2,%3}, {%4,%5,%6,%7}, {%8,%9}, {%0,%1,%2,%3};"
        : "+f"(c[0]), "+f"(c[1]), "+f"(c[2]), "+f"(c[3])
        : "r"(a[0]), "r"(a[1]), "r"(a[2]), "r"(a[3]), "r"(b0), "r"(b1));
}

__device__ __forceinline__ void ldsm4(uint32_t& r0, uint32_t& r1, uint32_t& r2, uint32_t& r3,
                                      uint32_t addr) {
    asm volatile("ldmatrix.sync.aligned.m8n8.x4.shared.b16 {%0,%1,%2,%3}, [%4];"
                 : "=r"(r0), "=r"(r1), "=r"(r2), "=r"(r3) : "r"(addr));
}

__device__ __forceinline__ void ldsm4t(uint32_t& r0, uint32_t& r1, uint32_t& r2, uint32_t& r3,
                                       uint32_t addr) {
    asm volatile("ldmatrix.sync.aligned.m8n8.x4.trans.shared.b16 {%0,%1,%2,%3}, [%4];"
                 : "=r"(r0), "=r"(r1), "=r"(r2), "=r"(r3) : "r"(addr));
}

__device__ __forceinline__ void cp16(uint32_t dst, const void* src) {
    asm volatile("cp.async.ca.shared.global [%0], [%1], 16;" :: "r"(dst), "l"(src));
}

// ---------------- fp16 tensor-core GEMM:  C = A @ B^T (+bias)(+relu) ----------------
// AHF=1: A is fp16 [M,K] (raw copy staging, 16 halves per thread).
// AHF=0: A fp32 (cvt on staging). Fragments via ldmatrix.
template <int EPI, int OUTHF, int AHF>
__global__ void __launch_bounds__(256) tc_gemm(
    const void* __restrict__ Av, int lda,
    const float* __restrict__ B, int ldb,
    const float* __restrict__ bias,
    void* __restrict__ Cv, int ldc, int K)
{
    constexpr int BM = 128, BN = 64, BK = 32, ST = 20;
    __shared__ uint32_t As[BM * ST];
    __shared__ uint32_t Bs[BN * ST];
    const uint32_t sAs = (uint32_t)__cvta_generic_to_shared(As);
    const uint32_t sBs = (uint32_t)__cvta_generic_to_shared(Bs);

    const int bm = blockIdx.y * BM;
    const int bn = blockIdx.x * BN;
    const int tid = threadIdx.x;
    const int lane = tid & 31;
    const int warp = tid >> 5;
    const int wm = (warp & 3) * 32;
    const int wn = (warp >> 2) * 32;
    const int gr = lane >> 2;
    const int gc = lane & 3;
    const int mhi = lane >> 3;
    const int r8 = lane & 7;

    float acc[2][4][4];
#pragma unroll
    for (int mt = 0; mt < 2; mt++)
#pragma unroll
        for (int nt = 0; nt < 4; nt++)
#pragma unroll
            for (int q = 0; q < 4; q++) acc[mt][nt][q] = 0.f;

    for (int kt = 0; kt < K; kt += BK) {
        if (AHF) {
            const __half* A = (const __half*)Av;
            const int m = tid >> 1;
            const int kh = (tid & 1) * 16;
            const __half* p = A + (size_t)(bm + m) * lda + kt + kh;
            const uint4 v0 = *reinterpret_cast<const uint4*>(p);
            const uint4 v1 = *reinterpret_cast<const uint4*>(p + 8);
            uint32_t* s = &As[m * ST + kh / 2];
            s[0] = v0.x; s[1] = v0.y; s[2] = v0.z; s[3] = v0.w;
            s[4] = v1.x; s[5] = v1.y; s[6] = v1.z; s[7] = v1.w;
        } else {
            const float* A = (const float*)Av;
            const int m = tid >> 1;
            const int kh = (tid & 1) * 16;
            const float* p = A + (size_t)(bm + m) * lda + kt + kh;
            uint32_t* s = &As[m * ST + kh / 2];
#pragma unroll
            for (int j = 0; j < 4; j++) {
                float4 v = *reinterpret_cast<const float4*>(p + j * 4);
                s[j * 2 + 0] = packhf(v.x, v.y);
                s[j * 2 + 1] = packhf(v.z, v.w);
            }
        }
        {
            const int n = tid >> 2;
            const int kh = (tid & 3) * 8;
            const float* p = B + (size_t)(bn + n) * ldb + kt + kh;
            uint32_t* s = &Bs[n * ST + kh / 2];
            float4 v0 = *reinterpret_cast<const float4*>(p);
            float4 v1 = *reinterpret_cast<const float4*>(p + 4);
            s[0] = packhf(v0.x, v0.y);
            s[1] = packhf(v0.z, v0.w);
            s[2] = packhf(v1.x, v1.y);
            s[3] = packhf(v1.z, v1.w);
        }
        __syncthreads();

#pragma unroll
        for (int kc = 0; kc < 2; kc++) {
            // A fragments: m16k16 per mt via ldmatrix.x4
            uint32_t af[2][4];
#pragma unroll
            for (int mt = 0; mt < 2; mt++) {
                const int row = wm + mt * 16 + (mhi & 1) * 8 + r8;
                ldsm4(af[mt][0], af[mt][1], af[mt][2], af[mt][3],
                      sAs + (row * ST + kc * 8 + (mhi >> 1) * 4) * 4);
            }
            // B fragments: two n8k16 tiles per ldmatrix.x4 (flash-QK^T layout)
#pragma unroll
            for (int nc = 0; nc < 2; nc++) {
                const int row = wn + nc * 16 + (mhi >> 1) * 8 + r8;
                uint32_t b0, b1, b2, b3;
                ldsm4(b0, b1, b2, b3,
                      sBs + (row * ST + kc * 8 + (mhi & 1) * 4) * 4);
#pragma unroll
                for (int mt = 0; mt < 2; mt++) {
                    mma_f16(acc[mt][2 * nc], af[mt], b0, b1);
                    mma_f16(acc[mt][2 * nc + 1], af[mt], b2, b3);
                }
            }
        }
        __syncthreads();
    }

#pragma unroll
    for (int mt = 0; mt < 2; mt++) {
#pragma unroll
        for (int nt = 0; nt < 4; nt++) {
            const int col = bn + wn + nt * 8 + gc * 2;
            float bx = 0.f, by = 0.f;
            if (EPI >= 1) { bx = bias[col]; by = bias[col + 1]; }
#pragma unroll
            for (int half = 0; half < 2; half++) {
                const int row = bm + wm + mt * 16 + gr + half * 8;
                float v0 = acc[mt][nt][half * 2 + 0];
                float v1 = acc[mt][nt][half * 2 + 1];
                if (EPI >= 1) { v0 += bx; v1 += by; }
                if (EPI == 2) { v0 = fmaxf(v0, 0.f); v1 = fmaxf(v1, 0.f); }
                if (OUTHF) {
                    __half* C = (__half*)Cv;
                    *reinterpret_cast<uint32_t*>(&C[(size_t)row * ldc + col]) = packhf(v0, v1);
                } else {
                    float* C = (float*)Cv;
                    *reinterpret_cast<float2*>(&C[(size_t)row * ldc + col]) = make_float2(v0, v1);
                }
            }
        }
    }
}

// ---------------- fused flash attention: fp16 mma, shift-free softmax ----------------
__device__ __forceinline__ void kv_prefetch(const __half* __restrict__ qkvh,
                                            int h, int t, uint32_t stage, int tid) {
    const int r16 = tid >> 3;
    const int c8 = tid & 7;
#pragma unroll
    for (int p = 0; p < 8; p++) {
        int row = p * 16 + r16;
        const __half* base =
            qkvh + (size_t)(t * FBN_ + row) * (3 * HID_) + h * DH_ + c8 * 8;
        uint32_t d = stage + (row * KST_ + c8 * 4) * 4;
        cp16(d, base + HID_);              // K
        cp16(d + TILEB_, base + 2 * HID_); // V
    }
}

__global__ void __launch_bounds__(128) flash_attn(
    const __half* __restrict__ qkvh, __half* __restrict__ attn)
{
    extern __shared__ __align__(128) uint8_t smraw[];
    const uint32_t sbase = (uint32_t)__cvta_generic_to_shared(smraw);

    const int h = blockIdx.y;
    const int q0 = blockIdx.x * FBM_;
    const int tid = threadIdx.x;
    const int lane = tid & 31;
    const int warp = tid >> 5;
    const int gr = lane >> 2;
    const int gc = lane & 3;
    const int mhi = lane >> 3;
    const int r8 = lane & 7;
    const int wrow = warp * 16;
    const float c2 = 0.125f * LOG2E_;

    // ---- Q fragments (raw fp16) ----
    uint32_t qf[4][4];
    {
        const uint32_t* q0p = reinterpret_cast<const uint32_t*>(
            qkvh + (size_t)(q0 + wrow + gr) * (3 * HID_) + h * DH_);
        const uint32_t* q1p = reinterpret_cast<const uint32_t*>(
            qkvh + (size_t)(q0 + wrow + gr + 8) * (3 * HID_) + h * DH_);
#pragma unroll
        for (int kc = 0; kc < 4; kc++) {
            qf[kc][0] = q0p[kc * 8 + gc];
            qf[kc][1] = q1p[kc * 8 + gc];
            qf[kc][2] = q0p[kc * 8 + gc + 4];
            qf[kc][3] = q1p[kc * 8 + gc + 4];
        }
    }

    float o[8][4];
#pragma unroll
    for (int nt = 0; nt < 8; nt++)
#pragma unroll
        for (int q = 0; q < 4; q++) o[nt][q] = 0.f;
    float l0 = 0.f, l1 = 0.f;

    kv_prefetch(qkvh, h, 0, sbase, tid);
    asm volatile("cp.async.commit_group;");

    for (int t = 0; t < NT_; t++) {
        if (t + 1 < NT_)
            kv_prefetch(qkvh, h, t + 1, sbase + ((t + 1) & 1) * STAGEB_, tid);
        asm volatile("cp.async.commit_group;");
        asm volatile("cp.async.wait_group 1;");
        __syncthreads();

        const uint32_t sK = sbase + (t & 1) * STAGEB_;
        const uint32_t sV = sK + TILEB_;

        // ---- S = Q @ K^T via ldmatrix.x4 ----
        float cf[16][4];
#pragma unroll
        for (int nt = 0; nt < 16; nt++)
#pragma unroll
            for (int q = 0; q < 4; q++) cf[nt][q] = 0.f;
#pragma unroll
        for (int kc = 0; kc < 4; kc++) {
#pragma unroll
            for (int ntp = 0; ntp < 8; ntp++) {
                const int row = ntp * 16 + (mhi >> 1) * 8 + r8;
                const uint32_t addr = sK + (row * KST_ + kc * 8 + (mhi & 1) * 4) * 4;
                uint32_t b0, b1, b2, b3;
                ldsm4(b0, b1, b2, b3, addr);
                mma_f16(cf[2 * ntp], qf[kc], b0, b1);
                mma_f16(cf[2 * ntp + 1], qf[kc], b2, b3);
            }
        }

        // ---- shift-free softmax: p = exp2(c2 * s), fp16x2 ----
        uint32_t pf[8][4];
        __half2 hs0[4], hs1[4];
#pragma unroll
        for (int i = 0; i < 4; i++) {
            hs0[i] = __half2half2(__ushort_as_half(0));
            hs1[i] = __half2half2(__ushort_as_half(0));
        }
#pragma unroll
        for (int nt = 0; nt < 16; nt++) {
            uint32_t p0 = ex2h2(packhf(c2 * cf[nt][0], c2 * cf[nt][1]));
            uint32_t p1 = ex2h2(packhf(c2 * cf[nt][2], c2 * cf[nt][3]));
            hs0[nt & 3] = __hadd2(hs0[nt & 3], *reinterpret_cast<__half2*>(&p0));
            hs1[nt & 3] = __hadd2(hs1[nt & 3], *reinterpret_cast<__half2*>(&p1));
            if ((nt & 1) == 0) {
                pf[nt >> 1][0] = p0;
                pf[nt >> 1][1] = p1;
            } else {
                pf[nt >> 1][2] = p0;
                pf[nt >> 1][3] = p1;
            }
        }
        float sum0 = 0.f, sum1 = 0.f;
#pragma unroll
        for (int i = 0; i < 4; i++) {
            float2 a = __half22float2(hs0[i]);
            float2 b = __half22float2(hs1[i]);
            sum0 += a.x + a.y;
            sum1 += b.x + b.y;
        }
        l0 += sum0;
        l1 += sum1;

        // ---- O += P @ V via ldmatrix.x4.trans ----
#pragma unroll
        for (int kt = 0; kt < 8; kt++) {
#pragma unroll
            for (int np = 0; np < 4; np++) {
                const int row = kt * 16 + (mhi & 1) * 8 + r8;
                const uint32_t addr = sV + (row * KST_ + np * 8 + (mhi >> 1) * 4) * 4;
                uint32_t v0, v1, v2, v3;
                ldsm4t(v0, v1, v2, v3, addr);
                mma_f16(o[2 * np], pf[kt], v0, v1);
                mma_f16(o[2 * np + 1], pf[kt], v2, v3);
            }
        }
        __syncthreads();
    }

    // ---- cross-quad sum of l, then epilogue: O / l -> attn (fp16) ----
    l0 += __shfl_xor_sync(0xffffffffu, l0, 1);
    l0 += __shfl_xor_sync(0xffffffffu, l0, 2);
    l1 += __shfl_xor_sync(0xffffffffu, l1, 1);
    l1 += __shfl_xor_sync(0xffffffffu, l1, 2);
    float inv0 = 1.f / l0;
    float inv1 = 1.f / l1;
    __half* obase = attn + (size_t)(q0 + wrow) * HID_ + h * DH_;
#pragma unroll
    for (int nt = 0; nt < 8; nt++) {
        int col = nt * 8 + 2 * gc;
        *reinterpret_cast<uint32_t*>(obase + (size_t)gr * HID_ + col) =
            packhf(o[nt][0] * inv0, o[nt][1] * inv0);
        *reinterpret_cast<uint32_t*>(obase + (size_t)(gr + 8) * HID_ + col) =
            packhf(o[nt][2] * inv1, o[nt][3] * inv1);
    }
}

// ---------------- GCN aggregation (CSR gather, float4, 4-way unroll) ----------------
// OUTHF=1: write packed fp16 (uint2). OUTHF=0: write float4 (with optional sigmoid).
template <int OUTHF>
__global__ void gcn_aggregate4(const float4* __restrict__ h4, const float* __restrict__ bias,
                               void* __restrict__ outv, int dout4, int act)
{
    int c = blockIdx.x;
    int f = threadIdx.x;
    float dv = g_dinv[c];
    float s = dv * dv;
    float4 acc = h4[(size_t)c * dout4 + f];
    acc.x *= s; acc.y *= s; acc.z *= s; acc.w *= s;
    int e0 = g_rowptr[c], e1 = g_rowptr[c + 1];
    int e = e0;
    for (; e + 4 <= e1; e += 4) {
        int s0 = g_src[e], s1 = g_src[e + 1], s2 = g_src[e + 2], s3 = g_src[e + 3];
        float w0 = g_w[e], w1 = g_w[e + 1], w2 = g_w[e + 2], w3 = g_w[e + 3];
        float4 v0 = h4[(size_t)s0 * dout4 + f];
        float4 v1 = h4[(size_t)s1 * dout4 + f];
        float4 v2 = h4[(size_t)s2 * dout4 + f];
        float4 v3 = h4[(size_t)s3 * dout4 + f];
        acc.x += w0 * v0.x + w1 * v1.x + w2 * v2.x + w3 * v3.x;
        acc.y += w0 * v0.y + w1 * v1.y + w2 * v2.y + w3 * v3.y;
        acc.z += w0 * v0.z + w1 * v1.z + w2 * v2.z + w3 * v3.z;
        acc.w += w0 * v0.w + w1 * v1.w + w2 * v2.w + w3 * v3.w;
    }
    for (; e < e1; e++) {
        int s0 = g_src[e];
        float w0 = g_w[e];
        float4 v0 = h4[(size_t)s0 * dout4 + f];
        acc.x += w0 * v0.x; acc.y += w0 * v0.y;
        acc.z += w0 * v0.z; acc.w += w0 * v0.w;
    }
    const float4 b4 = *reinterpret_cast<const float4*>(bias + f * 4);
    acc.x += b4.x; acc.y += b4.y; acc.z += b4.z; acc.w += b4.w;
    if (act) {
        acc.x = 1.f / (1.f + __expf(-acc.x));
        acc.y = 1.f / (1.f + __expf(-acc.y));
        acc.z = 1.f / (1.f + __expf(-acc.z));
        acc.w = 1.f / (1.f + __expf(-acc.w));
    }
    if (OUTHF) {
        uint2 o;
        o.x = packhf(acc.x, acc.y);
        o.y = packhf(acc.z, acc.w);
        reinterpret_cast<uint2*>(outv)[(size_t)c * dout4 + f] = o;
    } else {
        reinterpret_cast<float4*>(outv)[(size_t)c * dout4 + f] = acc;
    }
}

// ---------------- host orchestration ----------------
static void run_mha(const __half* xh, __half* outbh,
                    const float* ipw, const float* ipb,
                    const float* opw, const float* opb,
                    __half* qkvh, __half* attnh)
{
    tc_gemm<1, 1, 1><<<dim3(12, 32), 256>>>(
        xh, HID_, ipw, HID_, ipb, qkvh, 3 * HID_, HID_);

    flash_attn<<<dim3(L_ / FBM_, HEADS_), 128, 2 * STAGEB_>>>(qkvh, attnh);

    tc_gemm<2, 1, 1><<<dim3(4, 32), 256>>>(
        attnh, HID_, opw, HID_, opb, outbh, HID_, HID_);
}

extern "C" void kernel_launch(void* const* d_in, const int* in_sizes, int n_in,
                              void* d_out, int out_size)
{
    const float* x_in = (const float*)d_in[0];
    const int*   ei   = (const int*)d_in[1];
    const float* ew   = (const float*)d_in[2];
    const float* W1   = (const float*)d_in[3];
    const float* b1   = (const float*)d_in[4];
    const float* W2   = (const float*)d_in[5];
    const float* b2   = (const float*)d_in[6];
    const float* W3   = (const float*)d_in[7];
    const float* b3   = (const float*)d_in[8];
    const float* ipw  = (const float*)d_in[9];
    const float* ipb  = (const float*)d_in[10];
    const float* opw  = (const float*)d_in[11];
    const float* opb  = (const float*)d_in[12];
    float* out = (float*)d_out;

    float *ph, *pw1t, *pw2t, *pw3t;
    __half *pqkvh, *pattnh, *pah, *pbh;
    cudaGetSymbolAddress((void**)&ph, g_h);
    cudaGetSymbolAddress((void**)&pah, g_ah);
    cudaGetSymbolAddress((void**)&pbh, g_bh);
    cudaGetSymbolAddress((void**)&pattnh, g_attnh);
    cudaGetSymbolAddress((void**)&pqkvh, g_qkvh);
    cudaGetSymbolAddress((void**)&pw1t, g_w1t);
    cudaGetSymbolAddress((void**)&pw2t, g_w2t);
    cudaGetSymbolAddress((void**)&pw3t, g_w3t);

    static cudaStream_t s2 = nullptr;
    static cudaEvent_t evFork = nullptr, evJoin = nullptr;
    if (s2 == nullptr) {
        cudaStreamCreateWithFlags(&s2, cudaStreamNonBlocking);
        cudaEventCreateWithFlags(&evFork, cudaEventDisableTiming);
        cudaEventCreateWithFlags(&evJoin, cudaEventDisableTiming);
        cudaFuncSetAttribute(flash_attn, cudaFuncAttributeMaxDynamicSharedMemorySize,
                             2 * STAGEB_);
    }

    // ---- fork: preproc chain on s2 || transposes + layer-1 GEMM on main stream ----
    cudaEventRecord(evFork, 0);
    cudaStreamWaitEvent(s2, evFork, 0);

    k_init<<<NN_ / 256, 256, 0, s2>>>();
    k_deg<<<EE_ / 256, 256, 0, s2>>>(ei, ew);
    k_dinv<<<NN_ / 256, 256, 0, s2>>>();
    k_scan<<<1, 256, 0, s2>>>();
    k_fill<<<EE_ / 256, 256, 0, s2>>>(ei, ew);
    cudaEventRecord(evJoin, s2);

    k_transpose3<<<dim3(8, 8, 3), dim3(32, 8)>>>(W1, pw1t, W2, pw2t, W3, pw3t);
    tc_gemm<0, 0, 0><<<dim3(HID_ / 64, NN_ / 128), 256>>>(
        x_in, 256, pw1t, 256, nullptr, ph, HID_, 256);

    cudaStreamWaitEvent(0, evJoin, 0);

    // --- layer 1: gcn aggregate (-> fp16 for mha) ---
    gcn_aggregate4<1><<<NN_, HID_ / 4>>>((const float4*)ph, b1, pah, HID_ / 4, 0);

    // --- mha 1 (with relu) ---
    run_mha(pah, pbh, ipw, ipb, opw, opb, pqkvh, pattnh);

    // --- layer 2: gcn ---
    tc_gemm<0, 0, 1><<<dim3(HID_ / 64, NN_ / 128), 256>>>(
        pbh, HID_, pw2t, HID_, nullptr, ph, HID_, HID_);
    gcn_aggregate4<1><<<NN_, HID_ / 4>>>((const float4*)ph, b2, pah, HID_ / 4, 0);

    // --- mha 2 (with relu) ---
    run_mha(pah, pbh, ipw, ipb, opw, opb, pqkvh, pattnh);

    // --- layer 3: gcn + sigmoid -> d_out (fp32) ---
    tc_gemm<0, 0, 1><<<dim3(DOUT_ / 64, NN_ / 128), 256>>>(
        pbh, HID_, pw3t, HID_, nullptr, ph, DOUT_, HID_);
    gcn_aggregate4<0><<<NN_, DOUT_ / 4>>>((const float4*)ph, b3, out, DOUT_ / 4, 1);
}